// round 4
// baseline (speedup 1.0000x reference)
#include <cuda_runtime.h>
#include <cuda_bf16.h>
#include <cstdint>

// Problem constants
#define Bb 4
#define Cc 3
#define Hh 1024
#define Ww 1024
#define NN (Hh * Ww)          // 2^20 pixels per image plane

// Single-flowset scratch: [B][N][4 channels (3 used + 1 pad)] = 64 MB.
// Fits in GB300's ~126 MB L2 -> atomics RMW stay in L2, reduce reads hit L2.
__device__ float g_warp[(size_t)Bb * NN * 4];
__device__ double g_acc;

// ---------------------------------------------------------------------------
// One 16B vector reduction atomic instead of 3 scalar atomics.
// ---------------------------------------------------------------------------
__device__ __forceinline__ void red_add_v4(float* addr, float a, float b, float c) {
    asm volatile("red.global.add.v4.f32 [%0], {%1, %2, %3, %4};"
                 :: "l"(addr), "f"(a), "f"(b), "f"(c), "f"(0.0f)
                 : "memory");
}

// ---------------------------------------------------------------------------
// Kernel: zero the 64 MB scratch (float4 stores).
// ---------------------------------------------------------------------------
__global__ void __launch_bounds__(256) zero_kernel() {
    const unsigned n4 = Bb * NN;   // 4M float4 groups
    unsigned i = blockIdx.x * 256u + threadIdx.x;
    float4* p = reinterpret_cast<float4*>(g_warp);
    if (i < n4) p[i] = make_float4(0.f, 0.f, 0.f, 0.f);
}

// Tiny kernel: reset the scalar accumulator (also pads the launch index so
// ncu -s 5 lands on splatB).
__global__ void zacc_kernel() { g_acc = 0.0; }

// ---------------------------------------------------------------------------
// Kernel: bilinear forward splat for ONE flowset. One thread per (batch,pixel).
//   f==0: scale = 1/t     (im0 splatted with flows[0])
//   f==1: scale = 1/(1-t) (im1 splatted with flows[1])
// ---------------------------------------------------------------------------
__global__ void __launch_bounds__(256) splat_kernel(
    const float* __restrict__ flow,   // [B, 2, H, W] (this flowset)
    const float* __restrict__ im,     // [B, C, H, W]
    const float* __restrict__ tv,     // [B]
    int f)
{
    const unsigned idx = blockIdx.x * 256u + threadIdx.x;   // < B*N = 4M
    const unsigned b = idx >> 20;
    const unsigned p = idx & (NN - 1u);
    const unsigned y = p >> 10;
    const unsigned x = p & 1023u;

    const float t = __ldg(&tv[b]);
    const float s = f ? (1.0f / (1.0f - t)) : (1.0f / t);

    const float* fl = flow + (size_t)b * (2u * NN);
    const float X = (float)x + s * __ldg(&fl[p]);
    const float Y = (float)y + s * __ldg(&fl[NN + p]);

    const float x0f = floorf(X), y0f = floorf(Y);
    const float fx = X - x0f,    fy = Y - y0f;
    const int   x0 = (int)x0f,   y0 = (int)y0f;

    const float* ip = im + (size_t)b * (Cc * NN) + p;
    const float c0 = __ldg(&ip[0]);
    const float c1 = __ldg(&ip[NN]);
    const float c2 = __ldg(&ip[2 * NN]);

    float* wbase = g_warp + (size_t)b * NN * 4u;

    const float wx0 = 1.0f - fx, wx1 = fx;
    const float wy0 = 1.0f - fy, wy1 = fy;
    const bool vx0 = (unsigned)x0       < (unsigned)Ww;
    const bool vx1 = (unsigned)(x0 + 1) < (unsigned)Ww;
    const bool vy0 = (unsigned)y0       < (unsigned)Hh;
    const bool vy1 = (unsigned)(y0 + 1) < (unsigned)Hh;

    if (vy0) {
        float* row = wbase + (size_t)y0 * (Ww * 4u);
        if (vx0) { const float w = wx0 * wy0; red_add_v4(row + 4 * x0,       w * c0, w * c1, w * c2); }
        if (vx1) { const float w = wx1 * wy0; red_add_v4(row + 4 * (x0 + 1), w * c0, w * c1, w * c2); }
    }
    if (vy1) {
        float* row = wbase + (size_t)(y0 + 1) * (Ww * 4u);
        if (vx0) { const float w = wx0 * wy1; red_add_v4(row + 4 * x0,       w * c0, w * c1, w * c2); }
        if (vx1) { const float w = wx1 * wy1; red_add_v4(row + 4 * (x0 + 1), w * c0, w * c1, w * c2); }
    }
}

// ---------------------------------------------------------------------------
// Kernel: L1 reduction over range [lo, hi) of (b,p) indices.
//   acc += sum_c |warp[i][c] - ref[b][c][p]|
// If ZERO, stores zeros back into the scratch (fused re-zero for the next
// pass, while the lines are still resident in L2).
// ---------------------------------------------------------------------------
template<bool ZERO>
__global__ void __launch_bounds__(256) reduce_kernel(
    const float* __restrict__ ref,   // opposite image [B, C, H, W]
    unsigned lo, unsigned hi)
{
    float acc = 0.0f;
    for (unsigned i = lo + blockIdx.x * 256u + threadIdx.x; i < hi;
         i += gridDim.x * 256u) {
        const unsigned b = i >> 20;
        const unsigned p = i & (NN - 1u);

        float4* wp = reinterpret_cast<float4*>(g_warp + (size_t)i * 4u);
        const float4 w = *wp;
        if (ZERO) *wp = make_float4(0.f, 0.f, 0.f, 0.f);

        const float* r = ref + (size_t)b * (Cc * NN) + p;
        acc += fabsf(w.x - __ldg(&r[0]))
             + fabsf(w.y - __ldg(&r[NN]))
             + fabsf(w.z - __ldg(&r[2 * NN]));
    }

    // warp reduce
    #pragma unroll
    for (int o = 16; o; o >>= 1) acc += __shfl_xor_sync(0xffffffffu, acc, o);

    __shared__ float ssum[8];
    if ((threadIdx.x & 31u) == 0u) ssum[threadIdx.x >> 5] = acc;
    __syncthreads();
    if (threadIdx.x < 8u) {
        float v = ssum[threadIdx.x];
        #pragma unroll
        for (int o = 4; o; o >>= 1) v += __shfl_xor_sync(0xffu, v, o);
        if (threadIdx.x == 0u) atomicAdd(&g_acc, (double)v);
    }
}

// ---------------------------------------------------------------------------
// Kernel: finalize. loss = total_sum / (B*C*H*W) (same divisor for both means)
// ---------------------------------------------------------------------------
__global__ void finalize_kernel(float* __restrict__ out) {
    out[0] = (float)(g_acc / (double)((size_t)Bb * Cc * NN));
}

// ---------------------------------------------------------------------------
// Launch sequence (8 kernels; index 5 == splatB so ncu -s 5 -c 1 profiles it):
//   0 zero_scratch  1 zero_acc  2 splatA  3 reduceA_h1(+zero)  4 reduceA_h2(+zero)
//   5 splatB        6 reduceB   7 finalize
// inputs: flows [2,B,2,H,W], im0 [B,C,H,W], im1 [B,C,H,W], t [B]; output: scalar
// ---------------------------------------------------------------------------
extern "C" void kernel_launch(void* const* d_in, const int* in_sizes, int n_in,
                              void* d_out, int out_size) {
    const float* flows = (const float*)d_in[0];
    const float* im0   = (const float*)d_in[1];
    const float* im1   = (const float*)d_in[2];
    const float* tv    = (const float*)d_in[3];
    float* out = (float*)d_out;

    const unsigned n  = Bb * NN;          // 4M items per pass
    const unsigned nb = n / 256u;         // 16384 blocks

    zero_kernel<<<nb, 256>>>();
    zacc_kernel<<<1, 1>>>();

    // Pass A: warp im0 with flows[0] * (1/t); compare against im1.
    splat_kernel<<<nb, 256>>>(flows, im0, tv, 0);
    reduce_kernel<true><<<1024, 256>>>(im1, 0u, n / 2u);
    reduce_kernel<true><<<1024, 256>>>(im1, n / 2u, n);

    // Pass B: warp im1 with flows[1] * (1/(1-t)); compare against im0.
    splat_kernel<<<nb, 256>>>(flows + (size_t)Bb * 2u * NN, im1, tv, 1);
    reduce_kernel<false><<<2048, 256>>>(im0, 0u, n);

    finalize_kernel<<<1, 1>>>(out);
}

// round 6
// speedup vs baseline: 1.6421x; 1.6421x over previous
#include <cuda_runtime.h>
#include <cuda_bf16.h>
#include <cstdint>

// Problem constants
#define Bb 4
#define Cc 3
#define Hh 1024
#define Ww 1024
#define NN (Hh * Ww)          // 2^20 pixels per image plane

// Scratch: [2 (flowset)][B][N][4 ch (3 used + pad)] = 128 MB.
// CUDA zero-initializes __device__ globals at module load; reduce_kernel
// re-zeros every group it reads, so the zero-on-entry invariant holds for
// every call (including graph replays) with NO separate zero pass.
__device__ float g_warp[(size_t)2 * Bb * NN * 4];
__device__ double g_acc;

// ---------------------------------------------------------------------------
// One 16B vector reduction atomic instead of 3 scalar atomics.
// ---------------------------------------------------------------------------
__device__ __forceinline__ void red_add_v4(float* addr, float a, float b, float c) {
    asm volatile("red.global.add.v4.f32 [%0], {%1, %2, %3, %4};"
                 :: "l"(addr), "f"(a), "f"(b), "f"(c), "f"(0.0f)
                 : "memory");
}

// L2-targeted 16B store (skip L1 write path for the re-zero).
__device__ __forceinline__ void stg_cg_v4_zero(float4* addr) {
    asm volatile("st.global.cg.v4.f32 [%0], {%1, %1, %1, %1};"
                 :: "l"(addr), "f"(0.0f) : "memory");
}

// Tiny kernel: reset the scalar accumulator.
__global__ void zacc_kernel() { g_acc = 0.0; }

// ---------------------------------------------------------------------------
// Splat helper: bilinear scatter of (c0,c1,c2) to the 4 neighbors of (X, Y).
// ---------------------------------------------------------------------------
__device__ __forceinline__ void splat_one(float* __restrict__ wbase,
                                          float X, float Y,
                                          float c0, float c1, float c2) {
    const float x0f = floorf(X), y0f = floorf(Y);
    const float fx = X - x0f,    fy = Y - y0f;
    const int   x0 = (int)x0f,   y0 = (int)y0f;

    const float wx0 = 1.0f - fx, wx1 = fx;
    const float wy0 = 1.0f - fy, wy1 = fy;
    const bool vx0 = (unsigned)x0       < (unsigned)Ww;
    const bool vx1 = (unsigned)(x0 + 1) < (unsigned)Ww;
    const bool vy0 = (unsigned)y0       < (unsigned)Hh;
    const bool vy1 = (unsigned)(y0 + 1) < (unsigned)Hh;

    if (vy0) {
        float* row = wbase + (size_t)y0 * (Ww * 4u);
        if (vx0) { const float w = wx0 * wy0; red_add_v4(row + 4 * x0,       w * c0, w * c1, w * c2); }
        if (vx1) { const float w = wx1 * wy0; red_add_v4(row + 4 * (x0 + 1), w * c0, w * c1, w * c2); }
    }
    if (vy1) {
        float* row = wbase + (size_t)(y0 + 1) * (Ww * 4u);
        if (vx0) { const float w = wx0 * wy1; red_add_v4(row + 4 * x0,       w * c0, w * c1, w * c2); }
        if (vx1) { const float w = wx1 * wy1; red_add_v4(row + 4 * (x0 + 1), w * c0, w * c1, w * c2); }
    }
}

// ---------------------------------------------------------------------------
// Splat: both flowsets, one thread per (flowset, batch, pixel-PAIR).
// float2 loads for flow + channels halve the front-end load/index work.
// ---------------------------------------------------------------------------
__global__ void __launch_bounds__(256) splat_kernel(
    const float* __restrict__ flows,   // [2, B, 2, H, W]
    const float* __restrict__ im0,     // [B, C, H, W]
    const float* __restrict__ im1,     // [B, C, H, W]
    const float* __restrict__ tv)      // [B]
{
    const unsigned idx = blockIdx.x * 256u + threadIdx.x;   // < 2*B*N/2 = 4M
    const unsigned f   = idx >> 21;                          // B*N/2 = 2^21
    const unsigned rem = idx & ((1u << 21) - 1u);
    const unsigned b   = rem >> 19;                          // N/2 = 2^19
    const unsigned p   = (rem & ((1u << 19) - 1u)) * 2u;     // even pixel
    const unsigned y   = p >> 10;
    const unsigned x   = p & 1023u;

    const float t = __ldg(&tv[b]);
    const float s = f ? (1.0f / (1.0f - t)) : (1.0f / t);

    const float* fl = flows + (size_t)(f * Bb + b) * 2u * NN;
    const float2 dx = *reinterpret_cast<const float2*>(fl + p);
    const float2 dy = *reinterpret_cast<const float2*>(fl + NN + p);

    const float* im = (f ? im1 : im0) + (size_t)b * (Cc * NN) + p;
    const float2 c0 = *reinterpret_cast<const float2*>(im);
    const float2 c1 = *reinterpret_cast<const float2*>(im + NN);
    const float2 c2 = *reinterpret_cast<const float2*>(im + 2 * NN);

    float* wbase = g_warp + (size_t)(f * Bb + b) * NN * 4u;

    splat_one(wbase, (float)x        + s * dx.x, (float)y + s * dy.x, c0.x, c1.x, c2.x);
    splat_one(wbase, (float)(x + 1u) + s * dx.y, (float)y + s * dy.y, c0.y, c1.y, c2.y);
}

// ---------------------------------------------------------------------------
// Reduce: one thread per pixel-PAIR (covers BOTH scratch halves), no loop.
// All memory ops are address-independent -> MLP ~10 per thread (fixes the
// measured issue=2.0% latency-bound reduce). Fused re-zero restores the
// zero-on-entry invariant while lines are L2-resident.
//   loss_sum += sum_c |warpA - im1| + |warpB - im0|
// ---------------------------------------------------------------------------
__global__ void __launch_bounds__(256) reduce_kernel(
    const float* __restrict__ im0,
    const float* __restrict__ im1)
{
    const unsigned i = blockIdx.x * 256u + threadIdx.x;     // < B*N/2 = 2M
    const unsigned b = i >> 19;
    const unsigned p = (i & ((1u << 19) - 1u)) * 2u;

    float4* pa = reinterpret_cast<float4*>(g_warp) + (size_t)b * NN + p;
    float4* pb = reinterpret_cast<float4*>(g_warp) + (size_t)(Bb + b) * NN + p;

    // Independent loads (batched before any use).
    const float4 wa0 = pa[0], wa1 = pa[1];
    const float4 wb0 = pb[0], wb1 = pb[1];

    const float* r1 = im1 + (size_t)b * (Cc * NN) + p;
    const float* r0 = im0 + (size_t)b * (Cc * NN) + p;
    const float2 a0 = *reinterpret_cast<const float2*>(r1);
    const float2 a1 = *reinterpret_cast<const float2*>(r1 + NN);
    const float2 a2 = *reinterpret_cast<const float2*>(r1 + 2 * NN);
    const float2 b0 = *reinterpret_cast<const float2*>(r0);
    const float2 b1 = *reinterpret_cast<const float2*>(r0 + NN);
    const float2 b2 = *reinterpret_cast<const float2*>(r0 + 2 * NN);

    // Fused re-zero (L2-targeted; lines are resident from the loads above).
    stg_cg_v4_zero(pa); stg_cg_v4_zero(pa + 1);
    stg_cg_v4_zero(pb); stg_cg_v4_zero(pb + 1);

    float acc = fabsf(wa0.x - a0.x) + fabsf(wa0.y - a1.x) + fabsf(wa0.z - a2.x)
              + fabsf(wa1.x - a0.y) + fabsf(wa1.y - a1.y) + fabsf(wa1.z - a2.y)
              + fabsf(wb0.x - b0.x) + fabsf(wb0.y - b1.x) + fabsf(wb0.z - b2.x)
              + fabsf(wb1.x - b0.y) + fabsf(wb1.y - b1.y) + fabsf(wb1.z - b2.y);

    // warp reduce
    #pragma unroll
    for (int o = 16; o; o >>= 1) acc += __shfl_xor_sync(0xffffffffu, acc, o);

    __shared__ float ssum[8];
    if ((threadIdx.x & 31u) == 0u) ssum[threadIdx.x >> 5] = acc;
    __syncthreads();
    if (threadIdx.x < 8u) {
        float v = ssum[threadIdx.x];
        #pragma unroll
        for (int o = 4; o; o >>= 1) v += __shfl_xor_sync(0xffu, v, o);
        if (threadIdx.x == 0u) atomicAdd(&g_acc, (double)v);
    }
}

// ---------------------------------------------------------------------------
// Finalize. loss = total_sum / (B*C*H*W)  (same divisor for both means)
// ---------------------------------------------------------------------------
__global__ void finalize_kernel(float* __restrict__ out) {
    out[0] = (float)(g_acc / (double)((size_t)Bb * Cc * NN));
}

// ---------------------------------------------------------------------------
// 4 launches per call: zacc(0) splat(1) reduce(2) finalize(3).
// Global launch #5 (ncu -s 5 -c 1) == replay-2's SPLAT -> splat profile.
// inputs: flows [2,B,2,H,W], im0 [B,C,H,W], im1 [B,C,H,W], t [B]; out: scalar
// ---------------------------------------------------------------------------
extern "C" void kernel_launch(void* const* d_in, const int* in_sizes, int n_in,
                              void* d_out, int out_size) {
    const float* flows = (const float*)d_in[0];
    const float* im0   = (const float*)d_in[1];
    const float* im1   = (const float*)d_in[2];
    const float* tv    = (const float*)d_in[3];
    float* out = (float*)d_out;

    zacc_kernel<<<1, 1>>>();
    splat_kernel<<<(2u * Bb * NN / 2u) / 256u, 256>>>(flows, im0, im1, tv);   // 16384 blocks
    reduce_kernel<<<(Bb * NN / 2u) / 256u, 256>>>(im0, im1);                  // 8192 blocks
    finalize_kernel<<<1, 1>>>(out);
}